// round 17
// baseline (speedup 1.0000x reference)
#include <cuda_runtime.h>
#include <cuda_fp16.h>
#include <mma.h>
#include <math.h>
#include <cstdint>

using namespace nvcuda;

#define BB 2
#define TT 2048
#define DD 1024
#define HH 16
#define HD 64
#define NROWS (BB*TT)      // 4096
#define WINDOW 128
#define MM (1024*1024)

// ---------------- scratch (device globals: allocation-free) ----------------
__device__ __half g_q[(size_t)BB*HH*TT*HD];   // normalized q (fp16)
__device__ __half g_k[(size_t)BB*HH*TT*HD];   // normalized k (fp16)
__device__ __half g_v[(size_t)BB*HH*TT*HD];   // v (fp16)
__device__ __half g_xh[(size_t)NROWS*DD];     // x (fp16)
__device__ __half g_wh[(size_t)4*MM];         // 32*W (fp16)
__device__ __half g_ath[(size_t)NROWS*DD];    // attention out (fp16)

__device__ __forceinline__ uint32_t smem_u32(const void* p){
    uint32_t a;
    asm("{ .reg .u64 t; cvta.to.shared.u64 t, %1; cvt.u32.u64 %0, t; }" : "=r"(a) : "l"(p));
    return a;
}
__device__ __forceinline__ void cp16(uint32_t s, const void* g){
    asm volatile("cp.async.cg.shared.global [%0], [%1], 16;" :: "r"(s), "l"(g));
}

// =====================================================================
// split prep: x -> fp16 ; W -> fp16(32*W)
// =====================================================================
__global__ void __launch_bounds__(256) split_kernel(
    const float* __restrict__ x,
    const float* __restrict__ wq, const float* __restrict__ wk,
    const float* __restrict__ wv, const float* __restrict__ wo)
{
    size_t fi = (size_t)blockIdx.x*256 + threadIdx.x;
    if (fi < 1048576){
        float4 v = ((const float4*)x)[fi];
        size_t e = fi*4;
        *(half2*)(g_xh+e)   = half2(__float2half(v.x), __float2half(v.y));
        *(half2*)(g_xh+e+2) = half2(__float2half(v.z), __float2half(v.w));
    } else {
        size_t r = fi - 1048576;
        int m = (int)(r >> 18);
        size_t base = r & 262143;
        const float* src = (m==0)?wq:(m==1)?wk:(m==2)?wv:wo;
        float4 v = ((const float4*)src)[base];
        size_t e = (size_t)m*MM + base*4;
        *(half2*)(g_wh+e)   = half2(__float2half(32.0f*v.x), __float2half(32.0f*v.y));
        *(half2*)(g_wh+e+2) = half2(__float2half(32.0f*v.z), __float2half(32.0f*v.w));
    }
}

// =====================================================================
// GEMM (plain fp16, fp32 acc), 2 CTAs/SM.
// NEW: 128 threads / 4 warps, warp grid 2x2, warp tile 64x64.
// Fragment traffic per wmma: 256B (was 384B) — targets the smem co-bound.
// CTA tile 128x128, BK=64, 2-stage cp.async. smem 73728 B -> 2 CTAs/SM.
// =====================================================================
#define NCH 16
#define SSTRIDE 72
#define SARR 9216                        // 128 rows x 72 el
#define STAGE_EL (2*SARR)                // 18432 el
#define STAGE_BY (STAGE_EL*2)            // 36864 B
#define GEMM_SMEM 73728

__global__ void __launch_bounds__(128, 2) gemm_kernel(float* __restrict__ out, int mode)
{
    extern __shared__ __half sb[];
    float* Cs = (float*)sb;                       // [128][132] after mainloop

    const int tid = threadIdx.x, w = tid >> 5, lane = tid & 31;
    const int r0 = blockIdx.y * 128;
    const int nb = blockIdx.x * 128;

    int which, col0;
    const __half* A_h;
    if (mode == 0){ which = nb >> 10; col0 = nb & 1023; A_h = g_xh; }
    else          { which = 3;        col0 = nb;        A_h = g_ath; }
    const __half* W_h = g_wh + (size_t)which*MM;

    const uint32_t ab = smem_u32(sb);

    auto loadc = [&](int c){
        uint32_t st = ab + (uint32_t)(c & 1) * STAGE_BY;
        int ko = c * 64;
        #pragma unroll
        for (int i = 0; i < 8; i++){
            int idx = tid + i*128;                 // 0..1023: 128 rows x 8 segs
            int row = idx >> 3, seg = idx & 7;
            uint32_t so = (uint32_t)(row*144 + seg*16);
            cp16(st + so,          A_h + (size_t)(r0  + row)*DD + ko + seg*8);
            cp16(st + 18432u + so, W_h + (size_t)(col0 + row)*DD + ko + seg*8);
        }
        asm volatile("cp.async.commit_group;");
    };

    wmma::fragment<wmma::accumulator,16,16,16,float> acc[4][4];
    #pragma unroll
    for (int i = 0; i < 4; i++)
        #pragma unroll
        for (int j = 0; j < 4; j++) wmma::fill_fragment(acc[i][j], 0.0f);

    const int wm = (w >> 1) * 64;      // warp M offset: 0/64
    const int wn = (w & 1) * 64;       // warp N offset: 0/64

    loadc(0);
    for (int c = 0; c < NCH; c++){
        if (c < NCH-1){
            loadc(c+1);
            asm volatile("cp.async.wait_group 1;");
        } else {
            asm volatile("cp.async.wait_group 0;");
        }
        __syncthreads();

        const __half* s = sb + (c & 1) * STAGE_EL;
        const __half* sA = s;
        const __half* sB = s + SARR;

        #pragma unroll
        for (int kk = 0; kk < 64; kk += 16){
            wmma::fragment<wmma::matrix_a,16,16,16,__half,wmma::row_major> af[4];
            wmma::fragment<wmma::matrix_b,16,16,16,__half,wmma::col_major> bf[4];
            #pragma unroll
            for (int i = 0; i < 4; i++)
                wmma::load_matrix_sync(af[i], sA + (wm + i*16)*SSTRIDE + kk, SSTRIDE);
            #pragma unroll
            for (int j = 0; j < 4; j++)
                wmma::load_matrix_sync(bf[j], sB + (wn + j*16)*SSTRIDE + kk, SSTRIDE);
            #pragma unroll
            for (int i = 0; i < 4; i++)
                #pragma unroll
                for (int j = 0; j < 4; j++)
                    wmma::mma_sync(acc[i][j], af[i], bf[j], acc[i][j]);
        }
        __syncthreads();
    }

    // stage C in smem [128][132]  (values 32x true)
    #pragma unroll
    for (int i = 0; i < 4; i++)
        #pragma unroll
        for (int j = 0; j < 4; j++)
            wmma::store_matrix_sync(Cs + (wm + i*16)*132 + wn + j*16,
                                    acc[i][j], 132, wmma::mem_row_major);
    __syncthreads();

    const float unsc = 0.03125f;   // 1/32
    #pragma unroll
    for (int rr = 0; rr < 32; rr++){
        int row = w*32 + rr;
        int gt = r0 + row;
        float v0 = Cs[row*132 + lane];
        float v1 = Cs[row*132 + lane + 32];
        float v2 = Cs[row*132 + lane + 64];
        float v3 = Cs[row*132 + lane + 96];
        if (mode == 0){
            float s0 = unsc, s1 = unsc;
            if (which < 2){
                float ssa = v0*v0 + v1*v1;
                float ssb = v2*v2 + v3*v3;
                #pragma unroll
                for (int o = 16; o; o >>= 1){
                    ssa += __shfl_xor_sync(0xffffffffu, ssa, o);
                    ssb += __shfl_xor_sync(0xffffffffu, ssb, o);
                }
                s0 = 1.0f / fmaxf(sqrtf(ssa), 1e-6f);
                s1 = 1.0f / fmaxf(sqrtf(ssb), 1e-6f);
            }
            int bq = gt >> 11, t = gt & (TT-1);
            __half* arr = (which==0) ? g_q : ((which==1) ? g_k : g_v);
            int hh0 = col0 >> 6;
            __half* d0 = arr + ((size_t)(bq*HH + hh0  )*TT + t)*HD;
            __half* d1 = arr + ((size_t)(bq*HH + hh0+1)*TT + t)*HD;
            d0[lane]      = __float2half(v0*s0);
            d0[lane + 32] = __float2half(v1*s0);
            d1[lane]      = __float2half(v2*s1);
            d1[lane + 32] = __float2half(v3*s1);
        } else {
            float* d = out + (size_t)gt*DD + nb;
            d[lane]      = v0*unsc;
            d[lane + 32] = v1*unsc;
            d[lane + 64] = v2*unsc;
            d[lane + 96] = v3*unsc;
        }
    }
}

// =====================================================================
// Attention (fp16 wmma), 512 threads, 2 BLOCKS/SM (90KB smem). frozen.
// =====================================================================
#define ATTN_SMEM_BYTES 90112

__global__ void __launch_bounds__(512, 2) attn_kernel()
{
    extern __shared__ __half sm[];
    __half* Qs = sm;                          // [64][72]
    __half* Ks = sm + 4608;                   // [192][72]
    __half* Vs = sm + 18432;                  // [192][72]
    __half* Sh = sm + 32256;                  // [64][200]
    float*  Os = (float*)(sm + 4608);         // [64][68] f32 overlays Ks

    const int tid = threadIdx.x, w = tid >> 5, lane = tid & 31;
    const int q0 = blockIdx.x * 64;
    const int h  = blockIdx.y, b = blockIdx.z;
    const size_t base = ((size_t)(b*HH + h)*TT)*HD;
    const __half* qb = g_q + base;
    const __half* kb = g_k + base;
    const __half* vb = g_v + base;

    const uint32_t ab = smem_u32(sm);

    {   // Q
        int row = tid >> 3, seg = tid & 7;
        cp16(ab + (uint32_t)(row*144 + seg*16), qb + (size_t)(q0 + row)*HD + seg*8);
    }
    if (q0 + 192 <= TT){
        #pragma unroll
        for (int it = 0; it < 3; it++){
            int idx = tid + it*512;
            int row = idx >> 3, seg = idx & 7;
            uint32_t so = (uint32_t)(row*144 + seg*16);
            size_t go = (size_t)(q0 + row)*HD + seg*8;
            cp16(ab + 9216u  + so, kb + go);
            cp16(ab + 36864u + so, vb + go);
        }
    } else {
        #pragma unroll
        for (int it = 0; it < 3; it++){
            int idx = tid + it*512;
            int row = idx >> 3, seg = idx & 7;
            uint32_t so = (uint32_t)(row*144 + seg*16);
            if (q0 + row < TT){
                size_t go = (size_t)(q0 + row)*HD + seg*8;
                cp16(ab + 9216u  + so, kb + go);
                cp16(ab + 36864u + so, vb + go);
            } else {
                uint4 z = make_uint4(0,0,0,0);
                *(uint4*)(Ks + row*72 + seg*8) = z;
                *(uint4*)(Vs + row*72 + seg*8) = z;
            }
        }
    }
    asm volatile("cp.async.commit_group;");
    asm volatile("cp.async.wait_group 0;");
    __syncthreads();

    const int wr = w & 3;
    const int wg = w >> 2;

    {   // S = Q @ K^T, fp16 accumulators, live tiles tc = wg*3+f
        wmma::fragment<wmma::accumulator,16,16,16,__half> acc[3];
        #pragma unroll
        for (int f = 0; f < 3; f++) wmma::fill_fragment(acc[f], __float2half(0.0f));
        #pragma unroll
        for (int d = 0; d < HD; d += 16){
            wmma::fragment<wmma::matrix_a,16,16,16,__half,wmma::row_major> af;
            wmma::load_matrix_sync(af, Qs + wr*16*72 + d, 72);
            #pragma unroll
            for (int f = 0; f < 3; f++){
                int tc = wg*3 + f;
                if (tc >= wr && tc <= wr + 8){
                    wmma::fragment<wmma::matrix_b,16,16,16,__half,wmma::col_major> bf;
                    wmma::load_matrix_sync(bf, Ks + tc*16*72 + d, 72);
                    wmma::mma_sync(acc[f], af, bf, acc[f]);
                }
            }
        }
        #pragma unroll
        for (int f = 0; f < 3; f++){
            int tc = wg*3 + f;
            if (tc >= wr && tc <= wr + 8)
                wmma::store_matrix_sync(Sh + wr*16*200 + tc*16, acc[f], 200,
                                        wmma::mem_row_major);
        }
    }
    __syncthreads();

    const float slope = exp2f(-8.0f * (float)h / 15.0f);
    float bias[4];
    #pragma unroll
    for (int i = 0; i < 4; i++) bias[i] = -(float)(lane + 32*i)*slope;

    #pragma unroll
    for (int rr = 0; rr < 4; rr++){
        int row = w*4 + rr;
        float p[4];
        float sum = 0.0f;
        #pragma unroll
        for (int i = 0; i < 4; i++){
            int col = row + lane + 32*i;
            bool ok = (q0 + col < TT);
            float pv = ok ? __expf(__half2float(Sh[row*200 + col]) + bias[i]) : 0.0f;
            p[i] = pv; sum += pv;
        }
        #pragma unroll
        for (int o = 16; o; o >>= 1) sum += __shfl_xor_sync(0xffffffffu, sum, o);
        float inv = 1.0f / sum;
        #pragma unroll
        for (int i = 0; i < 4; i++){
            int col = row + lane + 32*i;
            Sh[row*200 + col] = __float2half(p[i]*inv);
        }
        int lead = row & 15;
        if (lane < lead)      Sh[row*200 + (row & ~15) + lane] = __float2half(0.0f);
        if (lane < 16 - lead) Sh[row*200 + row + 128 + lane]   = __float2half(0.0f);
    }
    __syncthreads();

    {   // O = P @ V
        wmma::fragment<wmma::accumulator,16,16,16,float> acc;
        wmma::fill_fragment(acc, 0.0f);
        #pragma unroll
        for (int tj = 0; tj < 12; tj++){
            if (tj >= wr && tj <= wr + 8){
                wmma::fragment<wmma::matrix_a,16,16,16,__half,wmma::row_major> af;
                wmma::fragment<wmma::matrix_b,16,16,16,__half,wmma::row_major> bf;
                wmma::load_matrix_sync(af, Sh + wr*16*200 + tj*16, 200);
                wmma::load_matrix_sync(bf, Vs + tj*16*72 + wg*16, 72);
                wmma::mma_sync(acc, af, bf, acc);
            }
        }
        wmma::store_matrix_sync(Os + wr*16*68 + wg*16, acc, 68, wmma::mem_row_major);
    }
    __syncthreads();

    #pragma unroll
    for (int it = 0; it < 2; it++){
        int idx = tid + it*512;
        int row = idx >> 4, c4 = (idx & 15) << 2;
        float4 v = *(const float4*)(Os + row*68 + c4);
        size_t o = (size_t)(b*TT + q0 + row)*DD + h*HD + c4;
        *(half2*)(g_ath+o)   = half2(__float2half(v.x), __float2half(v.y));
        *(half2*)(g_ath+o+2) = half2(__float2half(v.z), __float2half(v.w));
    }
}

// =====================================================================
extern "C" void kernel_launch(void* const* d_in, const int* in_sizes, int n_in,
                              void* d_out, int out_size)
{
    const float* x  = (const float*)d_in[0];
    const float* Wq = (const float*)d_in[1];
    const float* Wk = (const float*)d_in[2];
    const float* Wv = (const float*)d_in[3];
    const float* Wo = (const float*)d_in[4];
    float* out = (float*)d_out;

    cudaFuncSetAttribute(gemm_kernel, cudaFuncAttributeMaxDynamicSharedMemorySize,
                         GEMM_SMEM);
    cudaFuncSetAttribute(attn_kernel, cudaFuncAttributeMaxDynamicSharedMemorySize,
                         ATTN_SMEM_BYTES);

    // 0) fp16 conversion of x and weights (x32)
    split_kernel<<<8192, 256>>>(x, Wq, Wk, Wv, Wo);
    // 1) fused QKV projection + per-head l2norm  [M=4096 x N=3072]
    gemm_kernel<<<dim3(24, 32), 128, GEMM_SMEM>>>(nullptr, 0);
    // 2) sliding-window attention per (b, h, 64-query tile)
    attn_kernel<<<dim3(TT/64, HH, BB), 512, ATTN_SMEM_BYTES>>>();
    // 3) output projection
    gemm_kernel<<<dim3(8, 32), 128, GEMM_SMEM>>>(out, 1);
}